// round 4
// baseline (speedup 1.0000x reference)
#include <cuda_runtime.h>
#include <cstdint>
#include <cstddef>

// ---------------------------------------------------------------------------
// Problem dims: y[4096,4096] = scale * x @ W^T + bias
// ---------------------------------------------------------------------------
#define TOKENS 4096
#define KDIM   4096
#define ODIM   4096

// GEMM tile config — int8 IMMA path (plain sm_103 target, no tcgen05)
#define BM 128
#define BN 128
#define BK 128                       // int8 elements == bytes, 128B rows (SW128)
#define STAGES 3
#define KT (KDIM / BK)               // 32 k-iterations

#define AH_BYTES (BM * BK)           // 16384
#define AL_BYTES (BM * BK)           // 16384
#define B_BYTES  (BN * BK)           // 16384
#define OFF_AH 0
#define OFF_AL AH_BYTES
#define OFF_B  (AH_BYTES + AL_BYTES)
#define STAGE_BYTES (AH_BYTES + AL_BYTES + B_BYTES)   // 49152
#define SMEM_TOTAL (STAGES * STAGE_BYTES)             // 147456

#define NTHREADS 256                 // 8 warps: 2(m) x 4(n), warp tile 64x32

// hi/lo int8 quantization of x: x ~= S1*h + S2*l  (exact to S2/2 = 9.3e-5)
#define S1 (6.0f / 127.0f)
#define S2 (S1 / 254.0f)

// ---------------------------------------------------------------------------
// Scratch (device globals: allocation-free per harness rules)
// ---------------------------------------------------------------------------
__device__ signed char g_xh8[(size_t)TOKENS * KDIM];   // hi int8 of x
__device__ signed char g_xl8[(size_t)TOKENS * KDIM];   // lo int8 of x
__device__ signed char g_w8 [(size_t)ODIM   * KDIM];   // ternary weights int8

// ---------------------------------------------------------------------------
// Helpers
// ---------------------------------------------------------------------------
__device__ __forceinline__ uint32_t smem_u32(const void* p) {
    uint32_t a;
    asm("{ .reg .u64 t; cvta.to.shared.u64 t, %1; cvt.u32.u64 %0, t; }" : "=r"(a) : "l"(p));
    return a;
}

// SW128 swizzle (Swizzle<3,4,3>): conflict-free ldmatrix on 128B rows
__device__ __forceinline__ uint32_t sw128(uint32_t off) {
    return off ^ ((off >> 3) & 0x70);
}

__device__ __forceinline__ void cp16(uint32_t dst, const void* src) {
    asm volatile("cp.async.cg.shared.global [%0], [%1], 16;" :: "r"(dst), "l"(src) : "memory");
}

__device__ __forceinline__ void ldsm4(uint32_t (&r)[4], uint32_t addr) {
    asm volatile("ldmatrix.sync.aligned.m8n8.x4.shared.b16 {%0,%1,%2,%3}, [%4];"
                 : "=r"(r[0]), "=r"(r[1]), "=r"(r[2]), "=r"(r[3]) : "r"(addr));
}

// int8 IMMA, s32 accumulate: 16x8x32 per instruction
__device__ __forceinline__ void imma16832(int* d, const uint32_t* a, uint32_t b0, uint32_t b1) {
    asm volatile(
        "mma.sync.aligned.m16n8k32.row.col.s32.s8.s8.s32 "
        "{%0,%1,%2,%3}, {%4,%5,%6,%7}, {%8,%9}, {%0,%1,%2,%3};"
        : "+r"(d[0]), "+r"(d[1]), "+r"(d[2]), "+r"(d[3])
        : "r"(a[0]), "r"(a[1]), "r"(a[2]), "r"(a[3]), "r"(b0), "r"(b1));
}

// ---------------------------------------------------------------------------
// Prologue kernel 1: x fp32 -> hi/lo int8 pair
// ---------------------------------------------------------------------------
__global__ void __launch_bounds__(256) quant_x_kernel(const float* __restrict__ x) {
    size_t i = ((size_t)blockIdx.x * 256 + threadIdx.x) * 8;
    float4 a = *(const float4*)(x + i);
    float4 b = *(const float4*)(x + i + 4);
    float v[8] = {a.x, a.y, a.z, a.w, b.x, b.y, b.z, b.w};
    union { signed char c[8]; uint2 u; } H, L;
    const float inv1 = 127.0f / 6.0f;
    const float inv2 = 1.0f / S2;
#pragma unroll
    for (int k = 0; k < 8; k++) {
        int h = __float2int_rn(v[k] * inv1);
        h = max(-127, min(127, h));
        float r = fmaf((float)h, -S1, v[k]);
        int l = __float2int_rn(r * inv2);
        l = max(-127, min(127, l));
        H.c[k] = (signed char)h;
        L.c[k] = (signed char)l;
    }
    *(uint2*)(g_xh8 + i) = H.u;
    *(uint2*)(g_xl8 + i) = L.u;
}

// ---------------------------------------------------------------------------
// Prologue kernel 2: bitmasks -> int8 W[ODIM][KDIM] (MSB-first bit order)
// ---------------------------------------------------------------------------
__global__ void __launch_bounds__(256) unpack_w_kernel(const int* __restrict__ pm,
                                                       const int* __restrict__ nm) {
    int id = blockIdx.x * 256 + threadIdx.x;     // [0, ODIM * KDIM/8)
    int p = pm[id], n = nm[id];
    union { signed char c[8]; uint2 u; } W;
#pragma unroll
    for (int k = 0; k < 8; k++) {
        W.c[k] = (signed char)(((p >> (7 - k)) & 1) - ((n >> (7 - k)) & 1));
    }
    *(uint2*)(g_w8 + (size_t)id * 8) = W.u;
}

// ---------------------------------------------------------------------------
// Stage loader: Ahi[128x128] + Alo[128x128] + B[128x128] int8, SW128 smem
// ---------------------------------------------------------------------------
__device__ __forceinline__ void load_stage(uint32_t sbase, int m0, int n0, int kb, int tid) {
#pragma unroll
    for (int i = 0; i < 4; i++) {                // 1024 x 16B chunks per region
        int idx = tid + i * NTHREADS;
        int r = idx >> 3, c = idx & 7;
        uint32_t so = sw128((uint32_t)(r * 128 + c * 16));
        size_t ga = (size_t)(m0 + r) * KDIM + kb + c * 16;
        cp16(sbase + OFF_AH + so, g_xh8 + ga);
        cp16(sbase + OFF_AL + so, g_xl8 + ga);
        cp16(sbase + OFF_B + so, g_w8 + (size_t)(n0 + r) * KDIM + kb + c * 16);
    }
}

// ---------------------------------------------------------------------------
// Main GEMM: two int8 passes (hi/lo) into two s32 accumulator sets.
// 8 warps (2m x 4n), warp tile 64x32, BK=128 = 4 k32-steps.
// ---------------------------------------------------------------------------
__global__ void __launch_bounds__(NTHREADS, 1)
ternary_gemm_kernel(const float* __restrict__ scale_p,
                    const float* __restrict__ bias,
                    float* __restrict__ out) {
    extern __shared__ char smem[];
    const uint32_t sb = smem_u32(smem);
    const int tid = threadIdx.x;
    const int lane = tid & 31, wid = tid >> 5;
    const int m0 = blockIdx.y * BM;
    const int n0 = blockIdx.x * BN;
    const int wm = (wid & 1) * 64;        // 2 m-warps
    const int wn = (wid >> 1) * 32;       // 4 n-warps

    int accH[4][4][4];                    // [mt][n8][reg], hi pass
    int accL[4][4][4];                    // lo pass
#pragma unroll
    for (int i = 0; i < 4; i++)
#pragma unroll
        for (int j = 0; j < 4; j++)
#pragma unroll
            for (int c = 0; c < 4; c++) { accH[i][j][c] = 0; accL[i][j][c] = 0; }

    const int mat = lane >> 3, lr = lane & 7;

    // ---- pipeline prologue ----
#pragma unroll
    for (int s = 0; s < STAGES - 1; s++) {
        load_stage(sb + s * STAGE_BYTES, m0, n0, s * BK, tid);
        asm volatile("cp.async.commit_group;" ::: "memory");
    }
    asm volatile("cp.async.wait_group %0;" :: "n"(STAGES - 2) : "memory");
    __syncthreads();

    int rs = 0, ws = STAGES - 1;

    for (int k = 0; k < KT; k++) {
        if (k + STAGES - 1 < KT)
            load_stage(sb + ws * STAGE_BYTES, m0, n0, (k + STAGES - 1) * BK, tid);
        asm volatile("cp.async.commit_group;" ::: "memory");

        const uint32_t base = sb + rs * STAGE_BYTES;
#pragma unroll
        for (int kt = 0; kt < 4; kt++) {
            uint32_t Ah[4][4], Al[4][4], Bf[2][4];
#pragma unroll
            for (int mt = 0; mt < 4; mt++) {
                int row = wm + mt * 16 + ((mat & 1) << 3) + lr;
                uint32_t off = sw128((uint32_t)(row * 128 + kt * 32 + ((mat >> 1) << 4)));
                ldsm4(Ah[mt], base + OFF_AH + off);
                ldsm4(Al[mt], base + OFF_AL + off);
            }
#pragma unroll
            for (int nt = 0; nt < 2; nt++) {
                int row = wn + nt * 16 + ((mat >> 1) << 3) + lr;
                uint32_t off = sw128((uint32_t)(row * 128 + kt * 32 + ((mat & 1) << 4)));
                ldsm4(Bf[nt], base + OFF_B + off);
            }
#pragma unroll
            for (int mt = 0; mt < 4; mt++) {
#pragma unroll
                for (int nt = 0; nt < 2; nt++) {
                    imma16832(accH[mt][nt * 2],     Ah[mt], Bf[nt][0], Bf[nt][1]);
                    imma16832(accH[mt][nt * 2 + 1], Ah[mt], Bf[nt][2], Bf[nt][3]);
                    imma16832(accL[mt][nt * 2],     Al[mt], Bf[nt][0], Bf[nt][1]);
                    imma16832(accL[mt][nt * 2 + 1], Al[mt], Bf[nt][2], Bf[nt][3]);
                }
            }
        }

        ws = rs;
        rs = (rs + 1) % STAGES;
        asm volatile("cp.async.wait_group %0;" :: "n"(STAGES - 2) : "memory");
        __syncthreads();
    }

    // ---- epilogue: y = (scale*S1)*hi + (scale*S2)*lo + bias ----
    const float scale = __ldg(scale_p);
    const float f1 = scale * S1;
    const float f2 = scale * S2;
#pragma unroll
    for (int mt = 0; mt < 4; mt++) {
        const int row = m0 + wm + mt * 16 + (lane >> 2);
#pragma unroll
        for (int n8 = 0; n8 < 4; n8++) {
            const int col = n0 + wn + n8 * 8 + (lane & 3) * 2;
            const float2 bb = *(const float2*)(bias + col);
            float2 v0, v1;
            v0.x = fmaf(f1, (float)accH[mt][n8][0], fmaf(f2, (float)accL[mt][n8][0], bb.x));
            v0.y = fmaf(f1, (float)accH[mt][n8][1], fmaf(f2, (float)accL[mt][n8][1], bb.y));
            v1.x = fmaf(f1, (float)accH[mt][n8][2], fmaf(f2, (float)accL[mt][n8][2], bb.x));
            v1.y = fmaf(f1, (float)accH[mt][n8][3], fmaf(f2, (float)accL[mt][n8][3], bb.y));
            *(float2*)(out + (size_t)row * ODIM + col)       = v0;
            *(float2*)(out + (size_t)(row + 8) * ODIM + col) = v1;
        }
    }
}

// ---------------------------------------------------------------------------
// Launch
// ---------------------------------------------------------------------------
extern "C" void kernel_launch(void* const* d_in, const int* in_sizes, int n_in,
                              void* d_out, int out_size) {
    const float* x     = (const float*)d_in[0];
    const int*   pm    = (const int*)d_in[1];
    const int*   nm    = (const int*)d_in[2];
    const float* scale = (const float*)d_in[3];
    const float* bias  = (const float*)d_in[4];
    float* out = (float*)d_out;

    (void)in_sizes; (void)n_in; (void)out_size;

    quant_x_kernel<<<(int)(((size_t)TOKENS * KDIM) / (256 * 8)), 256>>>(x);
    unpack_w_kernel<<<(ODIM * (KDIM / 8)) / 256, 256>>>(pm, nm);

    cudaFuncSetAttribute(ternary_gemm_kernel,
                         cudaFuncAttributeMaxDynamicSharedMemorySize, SMEM_TOTAL);
    dim3 grid(ODIM / BN, TOKENS / BM);   // (32, 32) = 1024 CTAs
    ternary_gemm_kernel<<<grid, NTHREADS, SMEM_TOTAL>>>(scale, bias, out);
}

// round 5
// speedup vs baseline: 3.9894x; 3.9894x over previous
#include <cuda_runtime.h>
#include <cuda_fp16.h>
#include <cstdint>
#include <cstddef>

// ---------------------------------------------------------------------------
// Problem dims: y[4096,4096] = scale * x @ W^T + bias
// ---------------------------------------------------------------------------
#define TOKENS 4096
#define KDIM   4096
#define ODIM   4096

// GEMM tile config (legacy fp16 mma.sync; plain sm_103 target, no tcgen05)
#define BM 128
#define BN 128
#define BK 64
#define STAGES 3
#define KT (KDIM / BK)              // 64 k-iterations

#define A_BYTES (BM * BK * 2)       // 16384
#define B_BYTES (BN * BK * 2)       // 16384
#define STAGE_BYTES (A_BYTES + B_BYTES)      // 32768
#define SMEM_TOTAL (STAGES * STAGE_BYTES)    // 98304

#define NTHREADS 512                // 16 warps: 2(m) x 8(n), warp tile 64x16

// ---------------------------------------------------------------------------
// Scratch (device globals: allocation-free per harness rules)
// ---------------------------------------------------------------------------
__device__ __half g_xh[(size_t)TOKENS * KDIM];   // x rounded to fp16
__device__ __half g_w [(size_t)ODIM   * KDIM];   // ternary weights in fp16

// ---------------------------------------------------------------------------
// Helpers
// ---------------------------------------------------------------------------
__device__ __forceinline__ uint32_t smem_u32(const void* p) {
    uint32_t a;
    asm("{ .reg .u64 t; cvta.to.shared.u64 t, %1; cvt.u32.u64 %0, t; }" : "=r"(a) : "l"(p));
    return a;
}

// SW128 swizzle (Swizzle<3,4,3>): conflict-free ldmatrix on 128B rows
__device__ __forceinline__ uint32_t sw128(uint32_t off) {
    return off ^ ((off >> 3) & 0x70);
}

__device__ __forceinline__ void cp16(uint32_t dst, const void* src) {
    asm volatile("cp.async.cg.shared.global [%0], [%1], 16;" :: "r"(dst), "l"(src) : "memory");
}

__device__ __forceinline__ void ldsm4(uint32_t (&r)[4], uint32_t addr) {
    asm volatile("ldmatrix.sync.aligned.m8n8.x4.shared.b16 {%0,%1,%2,%3}, [%4];"
                 : "=r"(r[0]), "=r"(r[1]), "=r"(r[2]), "=r"(r[3]) : "r"(addr));
}

// fp16 inputs, fp32 accumulate (same tensor rate as f16-acc on sm_103)
__device__ __forceinline__ void mma16816(float* c, const uint32_t* a, uint32_t b0, uint32_t b1) {
    asm volatile(
        "mma.sync.aligned.m16n8k16.row.col.f32.f16.f16.f32 "
        "{%0,%1,%2,%3}, {%4,%5,%6,%7}, {%8,%9}, {%0,%1,%2,%3};"
        : "+f"(c[0]), "+f"(c[1]), "+f"(c[2]), "+f"(c[3])
        : "r"(a[0]), "r"(a[1]), "r"(a[2]), "r"(a[3]), "r"(b0), "r"(b1));
}

// ---------------------------------------------------------------------------
// Fused prologue: blocks [0, 8192)  -> x fp32 -> fp16 (8 elems/thread)
//                 blocks [8192, 16384) -> unpack masks -> fp16 W (8 elems/thread)
// ---------------------------------------------------------------------------
__global__ void __launch_bounds__(256) prologue_kernel(const float* __restrict__ x,
                                                       const int* __restrict__ pm,
                                                       const int* __restrict__ nm) {
    const int b = blockIdx.x;
    if (b < 8192) {
        size_t i = ((size_t)b * 256 + threadIdx.x) * 8;
        float4 a = *(const float4*)(x + i);
        float4 c = *(const float4*)(x + i + 4);
        float v[8] = {a.x, a.y, a.z, a.w, c.x, c.y, c.z, c.w};
        union { __half h[8]; uint4 u; } H;
#pragma unroll
        for (int k = 0; k < 8; k++) H.h[k] = __float2half_rn(v[k]);
        *(uint4*)(g_xh + i) = H.u;
    } else {
        int id = (b - 8192) * 256 + threadIdx.x;     // [0, ODIM * KDIM/8)
        int p = pm[id], n = nm[id];
        union { unsigned short h[8]; uint4 u; } W;
#pragma unroll
        for (int k = 0; k < 8; k++) {
            int pb = (p >> (7 - k)) & 1;             // MSB-first bit order
            int nb = (n >> (7 - k)) & 1;
            int t = pb - nb;                         // {-1, 0, +1}
            W.h[k] = (t == 0) ? (unsigned short)0
                              : ((t > 0) ? (unsigned short)0x3C00   // +1.0h
                                         : (unsigned short)0xBC00); // -1.0h
        }
        *(uint4*)(g_w + (size_t)id * 8) = W.u;
    }
}

// ---------------------------------------------------------------------------
// Stage loader: A[128x64] + B[128x64] fp16 into SW128 smem (512 threads)
// ---------------------------------------------------------------------------
__device__ __forceinline__ void load_stage(uint32_t sbase, int m0, int n0, int kb, int tid) {
#pragma unroll
    for (int i = 0; i < 2; i++) {                // A: 1024 x 16B chunks
        int idx = tid + i * NTHREADS;
        int r = idx >> 3, c = idx & 7;
        cp16(sbase + sw128((uint32_t)(r * 128 + c * 16)),
             g_xh + (size_t)(m0 + r) * KDIM + kb + c * 8);
    }
#pragma unroll
    for (int i = 0; i < 2; i++) {                // B: 1024 x 16B chunks
        int idx = tid + i * NTHREADS;
        int r = idx >> 3, c = idx & 7;
        cp16(sbase + A_BYTES + sw128((uint32_t)(r * 128 + c * 16)),
             g_w + (size_t)(n0 + r) * KDIM + kb + c * 8);
    }
}

// ---------------------------------------------------------------------------
// Fragment loader: one k16 step for a 64x16 warp tile
// ---------------------------------------------------------------------------
__device__ __forceinline__ void load_frags(uint32_t a_base, uint32_t b_base, int kt,
                                           int wm, int wn, int lane,
                                           uint32_t (&A)[4][4], uint32_t (&B)[4]) {
    const int mat = lane >> 3, lr = lane & 7;
#pragma unroll
    for (int mt = 0; mt < 4; mt++) {
        int row = wm + mt * 16 + ((mat & 1) << 3) + lr;
        uint32_t off = (uint32_t)(row * 128 + kt * 32 + ((mat >> 1) << 4));
        ldsm4(A[mt], a_base + sw128(off));
    }
    {
        int row = wn + ((mat >> 1) << 3) + lr;
        uint32_t off = (uint32_t)(row * 128 + kt * 32 + ((mat & 1) << 4));
        ldsm4(B, b_base + sw128(off));
    }
}

// ---------------------------------------------------------------------------
// Main GEMM: C[128,128] = A @ B^T, fp16 in / fp32 acc.
// 16 warps (2m x 8n), warp tile 64x16, 3-stage cp.async pipeline.
// ---------------------------------------------------------------------------
__global__ void __launch_bounds__(NTHREADS, 1)
ternary_gemm_kernel(const float* __restrict__ scale_p,
                    const float* __restrict__ bias,
                    float* __restrict__ out) {
    extern __shared__ char smem[];
    const uint32_t sb = smem_u32(smem);
    const int tid = threadIdx.x;
    const int lane = tid & 31, wid = tid >> 5;
    const int m0 = blockIdx.y * BM;
    const int n0 = blockIdx.x * BN;
    const int wm = (wid & 1) * 64;        // 2 m-warps
    const int wn = (wid >> 1) * 16;       // 8 n-warps

    // fp32 accumulators: [mt][n8][4] = 32 regs
    float acc[4][2][4];
#pragma unroll
    for (int i = 0; i < 4; i++)
#pragma unroll
        for (int j = 0; j < 2; j++)
#pragma unroll
            for (int c = 0; c < 4; c++) acc[i][j][c] = 0.0f;

    // ---- pipeline prologue ----
#pragma unroll
    for (int s = 0; s < STAGES - 1; s++) {
        load_stage(sb + s * STAGE_BYTES, m0, n0, s * BK, tid);
        asm volatile("cp.async.commit_group;" ::: "memory");
    }
    asm volatile("cp.async.wait_group %0;" :: "n"(STAGES - 2) : "memory");
    __syncthreads();

    int rs = 0, ws = STAGES - 1;

    for (int k = 0; k < KT; k++) {
        // prefetch stage k+STAGES-1
        if (k + STAGES - 1 < KT)
            load_stage(sb + ws * STAGE_BYTES, m0, n0, (k + STAGES - 1) * BK, tid);
        asm volatile("cp.async.commit_group;" ::: "memory");

        const uint32_t abase = sb + rs * STAGE_BYTES;
        const uint32_t bbase = abase + A_BYTES;

        uint32_t Af[2][4][4], Bf[2][4];
        load_frags(abase, bbase, 0, wm, wn, lane, Af[0], Bf[0]);
#pragma unroll
        for (int kt = 0; kt < 4; kt++) {
            if (kt < 3)
                load_frags(abase, bbase, kt + 1, wm, wn, lane, Af[(kt + 1) & 1], Bf[(kt + 1) & 1]);
            const int cur = kt & 1;
#pragma unroll
            for (int mt = 0; mt < 4; mt++) {
                mma16816(acc[mt][0], Af[cur][mt], Bf[cur][0], Bf[cur][1]);
                mma16816(acc[mt][1], Af[cur][mt], Bf[cur][2], Bf[cur][3]);
            }
        }

        ws = rs;
        rs = (rs + 1) % STAGES;
        asm volatile("cp.async.wait_group %0;" :: "n"(STAGES - 2) : "memory");
        __syncthreads();
    }

    // ---- epilogue: y = scale * acc + bias, direct float2 stores ----
    const float scale = __ldg(scale_p);
#pragma unroll
    for (int mt = 0; mt < 4; mt++) {
        const int row = m0 + wm + mt * 16 + (lane >> 2);
#pragma unroll
        for (int n8 = 0; n8 < 2; n8++) {
            const int col = n0 + wn + n8 * 8 + (lane & 3) * 2;
            const float2 bb = *(const float2*)(bias + col);
            float2 v0, v1;
            v0.x = fmaf(scale, acc[mt][n8][0], bb.x);
            v0.y = fmaf(scale, acc[mt][n8][1], bb.y);
            v1.x = fmaf(scale, acc[mt][n8][2], bb.x);
            v1.y = fmaf(scale, acc[mt][n8][3], bb.y);
            *(float2*)(out + (size_t)row * ODIM + col)       = v0;
            *(float2*)(out + (size_t)(row + 8) * ODIM + col) = v1;
        }
    }
}

// ---------------------------------------------------------------------------
// Launch
// ---------------------------------------------------------------------------
extern "C" void kernel_launch(void* const* d_in, const int* in_sizes, int n_in,
                              void* d_out, int out_size) {
    const float* x     = (const float*)d_in[0];
    const int*   pm    = (const int*)d_in[1];
    const int*   nm    = (const int*)d_in[2];
    const float* scale = (const float*)d_in[3];
    const float* bias  = (const float*)d_in[4];
    float* out = (float*)d_out;

    (void)in_sizes; (void)n_in; (void)out_size;

    // fused prologue: x->fp16 (first 8192 blocks) + mask unpack (next 8192)
    prologue_kernel<<<16384, 256>>>(x, pm, nm);

    cudaFuncSetAttribute(ternary_gemm_kernel,
                         cudaFuncAttributeMaxDynamicSharedMemorySize, SMEM_TOTAL);
    dim3 grid(ODIM / BN, TOKENS / BM);   // (32, 32) = 1024 CTAs
    ternary_gemm_kernel<<<grid, NTHREADS, SMEM_TOTAL>>>(scale, bias, out);
}

// round 6
// speedup vs baseline: 4.9021x; 1.2288x over previous
#include <cuda_runtime.h>
#include <cuda_fp16.h>
#include <cstdint>
#include <cstddef>

// ---------------------------------------------------------------------------
// Problem dims: y[4096,4096] = scale * x @ W^T + bias
// ---------------------------------------------------------------------------
#define TOKENS 4096
#define KDIM   4096
#define ODIM   4096

// GEMM tile config (legacy fp16 mma.sync; plain sm_103 target, no tcgen05)
#define BM 128
#define BN 256
#define BK 64
#define STAGES 3
#define KT (KDIM / BK)              // 64 k-iterations

#define A_BYTES (BM * BK * 2)       // 16384
#define B_BYTES (BN * BK * 2)       // 32768
#define STAGE_BYTES (A_BYTES + B_BYTES)      // 49152
#define SMEM_TOTAL (STAGES * STAGE_BYTES)    // 147456

#define NTHREADS 256                // 8 warps: 2(m) x 4(n), warp tile 64x64

// ---------------------------------------------------------------------------
// Scratch (device globals: allocation-free per harness rules)
// ---------------------------------------------------------------------------
__device__ __half g_xh[(size_t)TOKENS * KDIM];   // x rounded to fp16
__device__ __half g_w [(size_t)ODIM   * KDIM];   // ternary weights in fp16

// ---------------------------------------------------------------------------
// Helpers
// ---------------------------------------------------------------------------
__device__ __forceinline__ uint32_t smem_u32(const void* p) {
    uint32_t a;
    asm("{ .reg .u64 t; cvta.to.shared.u64 t, %1; cvt.u32.u64 %0, t; }" : "=r"(a) : "l"(p));
    return a;
}

// SW128 swizzle (Swizzle<3,4,3>): conflict-free ldmatrix on 128B rows
__device__ __forceinline__ uint32_t sw128(uint32_t off) {
    return off ^ ((off >> 3) & 0x70);
}

__device__ __forceinline__ void cp16(uint32_t dst, const void* src) {
    asm volatile("cp.async.cg.shared.global [%0], [%1], 16;" :: "r"(dst), "l"(src) : "memory");
}

__device__ __forceinline__ void ldsm4(uint32_t (&r)[4], uint32_t addr) {
    asm volatile("ldmatrix.sync.aligned.m8n8.x4.shared.b16 {%0,%1,%2,%3}, [%4];"
                 : "=r"(r[0]), "=r"(r[1]), "=r"(r[2]), "=r"(r[3]) : "r"(addr));
}

// fp16 inputs, fp32 accumulate
__device__ __forceinline__ void mma16816(float* c, const uint32_t* a, uint32_t b0, uint32_t b1) {
    asm volatile(
        "mma.sync.aligned.m16n8k16.row.col.f32.f16.f16.f32 "
        "{%0,%1,%2,%3}, {%4,%5,%6,%7}, {%8,%9}, {%0,%1,%2,%3};"
        : "+f"(c[0]), "+f"(c[1]), "+f"(c[2]), "+f"(c[3])
        : "r"(a[0]), "r"(a[1]), "r"(a[2]), "r"(a[3]), "r"(b0), "r"(b1));
}

// ---------------------------------------------------------------------------
// Fused prologue: blocks [0, 8192)   -> x fp32 -> fp16 (8 elems/thread)
//                 blocks [8192,16384)-> unpack masks -> fp16 W (8 elems/thread)
// ---------------------------------------------------------------------------
__global__ void __launch_bounds__(256) prologue_kernel(const float* __restrict__ x,
                                                       const int* __restrict__ pm,
                                                       const int* __restrict__ nm) {
    const int b = blockIdx.x;
    if (b < 8192) {
        size_t i = ((size_t)b * 256 + threadIdx.x) * 8;
        float4 a = *(const float4*)(x + i);
        float4 c = *(const float4*)(x + i + 4);
        float v[8] = {a.x, a.y, a.z, a.w, c.x, c.y, c.z, c.w};
        union { __half h[8]; uint4 u; } H;
#pragma unroll
        for (int k = 0; k < 8; k++) H.h[k] = __float2half_rn(v[k]);
        *(uint4*)(g_xh + i) = H.u;
    } else {
        int id = (b - 8192) * 256 + threadIdx.x;     // [0, ODIM * KDIM/8)
        int p = pm[id], n = nm[id];
        union { unsigned short h[8]; uint4 u; } W;
#pragma unroll
        for (int k = 0; k < 8; k++) {
            int pb = (p >> (7 - k)) & 1;             // MSB-first bit order
            int nb = (n >> (7 - k)) & 1;
            int t = pb - nb;                         // {-1, 0, +1}
            W.h[k] = (t == 0) ? (unsigned short)0
                              : ((t > 0) ? (unsigned short)0x3C00   // +1.0h
                                         : (unsigned short)0xBC00); // -1.0h
        }
        *(uint4*)(g_w + (size_t)id * 8) = W.u;
    }
}

// ---------------------------------------------------------------------------
// Stage loader: A[128x64] + B[256x64] fp16 into SW128 smem (256 threads)
// ---------------------------------------------------------------------------
__device__ __forceinline__ void load_stage(uint32_t sbase, int m0, int n0, int kb, int tid) {
#pragma unroll
    for (int i = 0; i < 4; i++) {                // A: 1024 x 16B chunks
        int idx = tid + i * NTHREADS;
        int r = idx >> 3, c = idx & 7;
        cp16(sbase + sw128((uint32_t)(r * 128 + c * 16)),
             g_xh + (size_t)(m0 + r) * KDIM + kb + c * 8);
    }
#pragma unroll
    for (int i = 0; i < 8; i++) {                // B: 2048 x 16B chunks
        int idx = tid + i * NTHREADS;
        int r = idx >> 3, c = idx & 7;
        cp16(sbase + A_BYTES + sw128((uint32_t)(r * 128 + c * 16)),
             g_w + (size_t)(n0 + r) * KDIM + kb + c * 8);
    }
}

// ---------------------------------------------------------------------------
// Main GEMM: C[128,256] = A @ B^T, fp16 in / fp32 acc.
// 8 warps (2m x 4n), warp tile 64x64, 3-stage cp.async pipeline.
// ---------------------------------------------------------------------------
__global__ void __launch_bounds__(NTHREADS, 1)
ternary_gemm_kernel(const float* __restrict__ scale_p,
                    const float* __restrict__ bias,
                    float* __restrict__ out) {
    extern __shared__ char smem[];
    const uint32_t sb = smem_u32(smem);
    const int tid = threadIdx.x;
    const int lane = tid & 31, wid = tid >> 5;
    const int m0 = blockIdx.y * BM;
    const int n0 = blockIdx.x * BN;
    const int wm = (wid & 1) * 64;        // 2 m-warps
    const int wn = (wid >> 1) * 64;       // 4 n-warps

    // fp32 accumulators: [mt][n8][4] = 128 regs
    float acc[4][8][4];
#pragma unroll
    for (int i = 0; i < 4; i++)
#pragma unroll
        for (int j = 0; j < 8; j++)
#pragma unroll
            for (int c = 0; c < 4; c++) acc[i][j][c] = 0.0f;

    const int mat = lane >> 3, lr = lane & 7;

    // ---- pipeline prologue ----
#pragma unroll
    for (int s = 0; s < STAGES - 1; s++) {
        load_stage(sb + s * STAGE_BYTES, m0, n0, s * BK, tid);
        asm volatile("cp.async.commit_group;" ::: "memory");
    }
    asm volatile("cp.async.wait_group %0;" :: "n"(STAGES - 2) : "memory");
    __syncthreads();

    int rs = 0, ws = STAGES - 1;

    for (int k = 0; k < KT; k++) {
        // prefetch stage k+STAGES-1
        if (k + STAGES - 1 < KT)
            load_stage(sb + ws * STAGE_BYTES, m0, n0, (k + STAGES - 1) * BK, tid);
        asm volatile("cp.async.commit_group;" ::: "memory");

        const uint32_t abase = sb + rs * STAGE_BYTES;
        const uint32_t bbase = abase + A_BYTES;

#pragma unroll
        for (int kt = 0; kt < 4; kt++) {
            uint32_t Af[4][4], Bf[4][4];
#pragma unroll
            for (int mt = 0; mt < 4; mt++) {
                int row = wm + mt * 16 + ((mat & 1) << 3) + lr;
                uint32_t off = (uint32_t)(row * 128 + kt * 32 + ((mat >> 1) << 4));
                ldsm4(Af[mt], abase + sw128(off));
            }
#pragma unroll
            for (int nt = 0; nt < 4; nt++) {
                int row = wn + nt * 16 + ((mat >> 1) << 3) + lr;
                uint32_t off = (uint32_t)(row * 128 + kt * 32 + ((mat & 1) << 4));
                ldsm4(Bf[nt], bbase + sw128(off));
            }
#pragma unroll
            for (int mt = 0; mt < 4; mt++) {
#pragma unroll
                for (int nt = 0; nt < 4; nt++) {
                    mma16816(acc[mt][nt * 2],     Af[mt], Bf[nt][0], Bf[nt][1]);
                    mma16816(acc[mt][nt * 2 + 1], Af[mt], Bf[nt][2], Bf[nt][3]);
                }
            }
        }

        ws = rs;
        rs = (rs + 1) % STAGES;
        asm volatile("cp.async.wait_group %0;" :: "n"(STAGES - 2) : "memory");
        __syncthreads();
    }

    // ---- epilogue: y = scale * acc + bias, direct float2 stores ----
    const float scale = __ldg(scale_p);
#pragma unroll
    for (int mt = 0; mt < 4; mt++) {
        const int row = m0 + wm + mt * 16 + (lane >> 2);
#pragma unroll
        for (int n8 = 0; n8 < 8; n8++) {
            const int col = n0 + wn + n8 * 8 + (lane & 3) * 2;
            const float2 bb = *(const float2*)(bias + col);
            float2 v0, v1;
            v0.x = fmaf(scale, acc[mt][n8][0], bb.x);
            v0.y = fmaf(scale, acc[mt][n8][1], bb.y);
            v1.x = fmaf(scale, acc[mt][n8][2], bb.x);
            v1.y = fmaf(scale, acc[mt][n8][3], bb.y);
            *(float2*)(out + (size_t)row * ODIM + col)       = v0;
            *(float2*)(out + (size_t)(row + 8) * ODIM + col) = v1;
        }
    }
}

// ---------------------------------------------------------------------------
// Launch
// ---------------------------------------------------------------------------
extern "C" void kernel_launch(void* const* d_in, const int* in_sizes, int n_in,
                              void* d_out, int out_size) {
    const float* x     = (const float*)d_in[0];
    const int*   pm    = (const int*)d_in[1];
    const int*   nm    = (const int*)d_in[2];
    const float* scale = (const float*)d_in[3];
    const float* bias  = (const float*)d_in[4];
    float* out = (float*)d_out;

    (void)in_sizes; (void)n_in; (void)out_size;

    // fused prologue: x->fp16 (first 8192 blocks) + mask unpack (next 8192)
    prologue_kernel<<<16384, 256>>>(x, pm, nm);

    cudaFuncSetAttribute(ternary_gemm_kernel,
                         cudaFuncAttributeMaxDynamicSharedMemorySize, SMEM_TOTAL);
    dim3 grid(ODIM / BN, TOKENS / BM);   // (16, 32) = 512 CTAs
    ternary_gemm_kernel<<<grid, NTHREADS, SMEM_TOTAL>>>(scale, bias, out);
}